// round 11
// baseline (speedup 1.0000x reference)
#include <cuda_runtime.h>
#include <cuda_bf16.h>
#include <cuda_fp16.h>
#include <math.h>

// Problem constants (fixed by the dataset)
#define NODES_MAX 100000
#define EDGES_MAX 1600000
#define F_IN   128
#define F_HID  64     // 32 half2 / 16 uint2
#define F_OUT  47
#define F_OUTP 48     // 24 half2 / 12 uint2

#define SCAN_TPB 512          // must be >= number of scan blocks (196)

typedef unsigned long long ull;

// ---------------------------------------------------------------------------
// f32x2 packed helpers (sm_100+ FFMA2 path — PTX only, per SASS_QUICKREF)
// ---------------------------------------------------------------------------
__device__ __forceinline__ ull pack2(float lo, float hi) {
    ull r; asm("mov.b64 %0, {%1, %2};" : "=l"(r) : "f"(lo), "f"(hi)); return r;
}
__device__ __forceinline__ void fma2(ull& acc, ull a, ull b) {
    asm("fma.rn.f32x2 %0, %1, %2, %0;" : "+l"(acc) : "l"(a), "l"(b));
}
__device__ __forceinline__ float2 unpack2(ull v) {
    float2 f; asm("mov.b64 {%0, %1}, %2;" : "=f"(f.x), "=f"(f.y) : "l"(v)); return f;
}

// ---------------------------------------------------------------------------
// Device scratch (no cudaMalloc allowed)
// ---------------------------------------------------------------------------
__device__ __half g_y1h[NODES_MAX * F_HID];   // x @ W1 (raw, fp16)
__device__ __half g_y2h[NODES_MAX * F_OUTP];  // (h @ W2) * dinv[row] (fp16), col 47 = 0
__device__ float  g_dinv[NODES_MAX];
__device__ int    g_degi[NODES_MAX];
__device__ int    g_off [NODES_MAX + 1];
__device__ int    g_cursor[NODES_MAX];
__device__ int    g_csrc[EDGES_MAX];          // CSR by dst: source node ids
__device__ int    g_bsum [SCAN_TPB];

// ---------------------------------------------------------------------------
// CSR build
// ---------------------------------------------------------------------------
__global__ void count4_kernel(const int* __restrict__ dst, int e4, int e) {
    int i = blockIdx.x * blockDim.x + threadIdx.x;
    if (i < e4) {
        int4 d = reinterpret_cast<const int4*>(dst)[i];
        atomicAdd(&g_degi[d.x], 1);
        atomicAdd(&g_degi[d.y], 1);
        atomicAdd(&g_degi[d.z], 1);
        atomicAdd(&g_degi[d.w], 1);
    }
    if (i == 0) {
        for (int k = e4 * 4; k < e; k++) atomicAdd(&g_degi[dst[k]], 1);
    }
}

// Stage 1: per-chunk (SCAN_TPB elems) partial sums.
__global__ __launch_bounds__(SCAN_TPB) void scan_partial_kernel(int n) {
    __shared__ int sred[SCAN_TPB];
    int t = threadIdx.x;
    int i = blockIdx.x * SCAN_TPB + t;
    sred[t] = (i < n) ? g_degi[i] : 0;
    __syncthreads();
    for (int o = SCAN_TPB / 2; o > 0; o >>= 1) {
        if (t < o) sred[t] += sred[t + o];
        __syncthreads();
    }
    if (t == 0) g_bsum[blockIdx.x] = sred[0];
}

// Stage 2 (fused tops+write): each block reduces the partials preceding it,
// then block-scans its own chunk and writes off/cursor/dinv.
__global__ __launch_bounds__(SCAN_TPB) void scan_write_kernel(int n, int e) {
    __shared__ int s[SCAN_TPB];
    __shared__ int base_sh;
    int t = threadIdx.x, bid = blockIdx.x;

    int v = (t < bid) ? g_bsum[t] : 0;
    s[t] = v;
    __syncthreads();
    for (int o = SCAN_TPB / 2; o > 0; o >>= 1) {
        if (t < o) s[t] += s[t + o];
        __syncthreads();
    }
    if (t == 0) base_sh = s[0];
    __syncthreads();
    int base = base_sh;
    __syncthreads();   // protect s[] reuse

    int i = bid * SCAN_TPB + t;
    int d = (i < n) ? g_degi[i] : 0;
    s[t] = d;
    __syncthreads();
    for (int o = 1; o < SCAN_TPB; o <<= 1) {
        int u = (t >= o) ? s[t - o] : 0;
        __syncthreads();
        s[t] += u;
        __syncthreads();
    }
    if (i < n) {
        int off = base + s[t] - d;     // exclusive prefix
        g_off[i] = off;
        g_cursor[i] = off;
        g_dinv[i] = rsqrtf((float)(d + 1));
    }
    if (bid == 0 && t == 0) g_off[n] = e;
}

__global__ void fill4_kernel(const int* __restrict__ src, const int* __restrict__ dst,
                             int e4, int e) {
    int i = blockIdx.x * blockDim.x + threadIdx.x;
    if (i < e4) {
        int4 d = reinterpret_cast<const int4*>(dst)[i];
        int4 sv = reinterpret_cast<const int4*>(src)[i];
        int p0 = atomicAdd(&g_cursor[d.x], 1);
        int p1 = atomicAdd(&g_cursor[d.y], 1);
        int p2 = atomicAdd(&g_cursor[d.z], 1);
        int p3 = atomicAdd(&g_cursor[d.w], 1);
        g_csrc[p0] = sv.x;
        g_csrc[p1] = sv.y;
        g_csrc[p2] = sv.z;
        g_csrc[p3] = sv.w;
    }
    if (i == 0) {
        for (int k = e4 * 4; k < e; k++) {
            int p = atomicAdd(&g_cursor[dst[k]], 1);
            g_csrc[p] = src[k];
        }
    }
}

// ---------------------------------------------------------------------------
// GEMM1: y1h[n,64] = fp16(x[n,128] @ W1[128,64])   (raw; dinv applied in agg1)
// ---------------------------------------------------------------------------
#define XS_LD 129
__global__ __launch_bounds__(256) void gemm1_kernel(const float* __restrict__ x,
                                                    const float* __restrict__ W1,
                                                    int n) {
    __shared__ float Ws[F_IN * F_HID];        // 32 KB, [k][c]
    __shared__ float Xs[32 * XS_LD];          // ~16.5 KB, [r][k] padded
    int tid = threadIdx.x;
    int row0 = blockIdx.x * 32;

    for (int i = tid; i < F_IN * F_HID; i += 256) Ws[i] = W1[i];
    for (int i = tid; i < 32 * F_IN; i += 256) {
        int r = i >> 7, k = i & 127;
        int gr = row0 + r;
        Xs[r * XS_LD + k] = (gr < n) ? x[gr * F_IN + k] : 0.f;
    }
    __syncthreads();

    int tx = tid & 15;        // cols tx*4 .. tx*4+3 (pairs 2tx, 2tx+1)
    int ty = tid >> 4;        // 0..15, rows ty*2, ty*2+1
    ull acc00 = 0, acc01 = 0, acc10 = 0, acc11 = 0;   // bits(0,0) = (0.f,0.f)
    const ull* Ws2 = reinterpret_cast<const ull*>(Ws);  // 32 pairs per k-row
    int r0 = ty * 2, r1 = ty * 2 + 1;
    #pragma unroll 4
    for (int k = 0; k < F_IN; k++) {
        ull w0 = Ws2[k * 32 + tx * 2];
        ull w1 = Ws2[k * 32 + tx * 2 + 1];
        float a0 = Xs[r0 * XS_LD + k];
        float a1 = Xs[r1 * XS_LD + k];
        ull a0p = pack2(a0, a0);
        ull a1p = pack2(a1, a1);
        fma2(acc00, a0p, w0); fma2(acc01, a0p, w1);
        fma2(acc10, a1p, w0); fma2(acc11, a1p, w1);
    }
    int gr0 = row0 + r0, gr1 = row0 + r1;
    uint2* yp = reinterpret_cast<uint2*>(g_y1h);   // 16 uint2 per row
    if (gr0 < n) {
        float2 c0 = unpack2(acc00), c1 = unpack2(acc01);
        __half2 p0 = __floats2half2_rn(c0.x, c0.y);
        __half2 p1 = __floats2half2_rn(c1.x, c1.y);
        uint2 u;
        u.x = *reinterpret_cast<unsigned int*>(&p0);
        u.y = *reinterpret_cast<unsigned int*>(&p1);
        yp[gr0 * 16 + tx] = u;
    }
    if (gr1 < n) {
        float2 c0 = unpack2(acc10), c1 = unpack2(acc11);
        __half2 p0 = __floats2half2_rn(c0.x, c0.y);
        __half2 p1 = __floats2half2_rn(c1.x, c1.y);
        uint2 u;
        u.x = *reinterpret_cast<unsigned int*>(&p0);
        u.y = *reinterpret_cast<unsigned int*>(&p1);
        yp[gr1 * 16 + tx] = u;
    }
}

// ---------------------------------------------------------------------------
// FUSED agg1 + GEMM2 (warp per dst node):
//   h = relu(dinv_d * (y1[d]*dinv_d + sum_s dinv_s*y1[s]) + b1)   [in-warp]
//   y2h[d] = fp16(dinv_d * (h @ W2pad))                            [fused]
// Aggregation: half-warp edge pairing over fp16 rows (as R8).
// GEMM2: h staged in per-warp SMEM (64 floats), W2 in block SMEM (12 KB,
// col 47 zero-padded). Lane l computes col l; lanes<16 also col 32+l.
// Removes the g_h global round-trip and the separate gemm2 launch.
// ---------------------------------------------------------------------------
__device__ __forceinline__ void acc4_fp16(float& f0, float& f1, float& f2, float& f3,
                                          uint2 a, float w) {
    __half2 h0 = *reinterpret_cast<__half2*>(&a.x);
    __half2 h1 = *reinterpret_cast<__half2*>(&a.y);
    float2 p0 = __half22float2(h0);
    float2 p1 = __half22float2(h1);
    f0 = fmaf(p0.x, w, f0); f1 = fmaf(p0.y, w, f1);
    f2 = fmaf(p1.x, w, f2); f3 = fmaf(p1.y, w, f3);
}

__global__ __launch_bounds__(256) void agg1g2_kernel(const float* __restrict__ b1,
                                                     const float* __restrict__ W2,
                                                     int n) {
    __shared__ float W2s[F_HID * F_OUTP];   // 12 KB, [k][c], col 47 = 0
    __shared__ float Hs[8][F_HID];          // 2 KB, per-warp hidden vector
    int tid = threadIdx.x;
    int wi = tid >> 5;                      // warp in block (0..7)
    int l = tid & 31;
    int w = blockIdx.x * 8 + wi;

    for (int i = tid; i < F_HID * F_OUTP; i += 256) {
        int k = i / F_OUTP, c = i - k * F_OUTP;
        W2s[i] = (c < F_OUT) ? W2[k * F_OUT + c] : 0.f;
    }
    __syncthreads();
    if (w >= n) return;

    int lh = l & 15, hh = l >> 4;
    const uint2* y = reinterpret_cast<const uint2*>(g_y1h);   // 16 per row

    // ---- aggregation (edge-paired half-warps, 4 LDG.64 in flight) ----
    float f0 = 0.f, f1 = 0.f, f2 = 0.f, f3 = 0.f;
    int beg = g_off[w], end = g_off[w + 1];
    for (int j = beg; j < end; j += 32) {
        int m = min(32, end - j);
        int idx = 0; float dv = 0.f;
        if (l < m) { idx = g_csrc[j + l]; dv = g_dinv[idx]; }
        int t = 0;
        for (; t + 7 < m; t += 8) {
            int   eA = t + hh, eB = t + 2 + hh, eC = t + 4 + hh, eD = t + 6 + hh;
            int   sA = __shfl_sync(0xFFFFFFFFu, idx, eA);
            float wA = __shfl_sync(0xFFFFFFFFu, dv,  eA);
            int   sB = __shfl_sync(0xFFFFFFFFu, idx, eB);
            float wB = __shfl_sync(0xFFFFFFFFu, dv,  eB);
            int   sC = __shfl_sync(0xFFFFFFFFu, idx, eC);
            float wC = __shfl_sync(0xFFFFFFFFu, dv,  eC);
            int   sD = __shfl_sync(0xFFFFFFFFu, idx, eD);
            float wD = __shfl_sync(0xFFFFFFFFu, dv,  eD);
            uint2 a = y[sA * 16 + lh];
            uint2 b = y[sB * 16 + lh];
            uint2 c = y[sC * 16 + lh];
            uint2 d = y[sD * 16 + lh];
            acc4_fp16(f0, f1, f2, f3, a, wA);
            acc4_fp16(f0, f1, f2, f3, b, wB);
            acc4_fp16(f0, f1, f2, f3, c, wC);
            acc4_fp16(f0, f1, f2, f3, d, wD);
        }
        for (; t + 3 < m; t += 4) {
            int   eA = t + hh, eB = t + 2 + hh;
            int   sA = __shfl_sync(0xFFFFFFFFu, idx, eA);
            float wA = __shfl_sync(0xFFFFFFFFu, dv,  eA);
            int   sB = __shfl_sync(0xFFFFFFFFu, idx, eB);
            float wB = __shfl_sync(0xFFFFFFFFu, dv,  eB);
            uint2 a = y[sA * 16 + lh];
            uint2 b = y[sB * 16 + lh];
            acc4_fp16(f0, f1, f2, f3, a, wA);
            acc4_fp16(f0, f1, f2, f3, b, wB);
        }
        for (; t < m; t += 2) {
            int   e0 = t + hh;
            int   se = min(e0, m - 1);
            int   s0 = __shfl_sync(0xFFFFFFFFu, idx, se);
            float w0 = __shfl_sync(0xFFFFFFFFu, dv,  se);
            if (e0 >= m) w0 = 0.f;
            uint2 a = y[s0 * 16 + lh];
            acc4_fp16(f0, f1, f2, f3, a, w0);
        }
    }
    f0 += __shfl_xor_sync(0xFFFFFFFFu, f0, 16);
    f1 += __shfl_xor_sync(0xFFFFFFFFu, f1, 16);
    f2 += __shfl_xor_sync(0xFFFFFFFFu, f2, 16);
    f3 += __shfl_xor_sync(0xFFFFFFFFu, f3, 16);

    float diw = g_dinv[w];
    uint2 sv = y[w * 16 + lh];            // self-loop term
    acc4_fp16(f0, f1, f2, f3, sv, diw);

    // ---- h = relu(dinv*acc + b1) -> per-warp SMEM ----
    if (l < 16) {
        float4 bb = reinterpret_cast<const float4*>(b1)[lh];
        float4 hv;
        hv.x = fmaxf(fmaf(diw, f0, bb.x), 0.f);
        hv.y = fmaxf(fmaf(diw, f1, bb.y), 0.f);
        hv.z = fmaxf(fmaf(diw, f2, bb.z), 0.f);
        hv.w = fmaxf(fmaf(diw, f3, bb.w), 0.f);
        *reinterpret_cast<float4*>(&Hs[wi][lh * 4]) = hv;
    }
    __syncwarp();

    // ---- fused GEMM2: lane l -> col l (0..31); lanes<16 also col 32+l ----
    float a0 = 0.f, a1 = 0.f;
    int c1idx = 32 + lh;                  // valid col for a1 (lanes<16 use it)
    #pragma unroll 8
    for (int k = 0; k < F_HID; k++) {
        float hk = Hs[wi][k];
        a0 = fmaf(hk, W2s[k * F_OUTP + l], a0);
        a1 = fmaf(hk, W2s[k * F_OUTP + c1idx], a1);
    }
    __half* yo = g_y2h + (size_t)w * F_OUTP;
    yo[l] = __float2half_rn(a0 * diw);
    if (l < 16) yo[32 + l] = __float2half_rn(a1 * diw);   // col 47 = 0 via W2s pad
}

// ---------------------------------------------------------------------------
// Aggregation layer 2 + bias + log_softmax (warp per node, fp16 gathers):
//   z[d] = dinv[d]*(sum y2[s] + y2[d]) + b2 ; out = z - logsumexp(z)
// ---------------------------------------------------------------------------
__global__ __launch_bounds__(256) void agg2_kernel(const float* __restrict__ b2,
                                                   float* __restrict__ out, int n) {
    int w = (blockIdx.x * blockDim.x + threadIdx.x) >> 5;
    int l = threadIdx.x & 31;
    if (w >= n) return;
    const __half2* y = reinterpret_cast<const __half2*>(g_y2h);   // 24 per row
    bool act = (l < 24);
    int lc = act ? l : 0;

    float2 acc = make_float2(0.f, 0.f);
    if (act) {
        float2 v = __half22float2(y[w * 24 + l]);
        acc = v;                                   // self term (y2 pre-scaled)
    }
    int beg = g_off[w], end = g_off[w + 1];
    for (int j = beg; j < end; j += 32) {
        int m = min(32, end - j);
        int idx = (l < m) ? g_csrc[j + l] : 0;
        int t = 0;
        for (; t + 3 < m; t += 4) {
            int s0 = __shfl_sync(0xFFFFFFFFu, idx, t    );
            int s1 = __shfl_sync(0xFFFFFFFFu, idx, t + 1);
            int s2 = __shfl_sync(0xFFFFFFFFu, idx, t + 2);
            int s3 = __shfl_sync(0xFFFFFFFFu, idx, t + 3);
            if (act) {
                float2 v0 = __half22float2(y[s0 * 24 + lc]);
                float2 v1 = __half22float2(y[s1 * 24 + lc]);
                float2 v2 = __half22float2(y[s2 * 24 + lc]);
                float2 v3 = __half22float2(y[s3 * 24 + lc]);
                acc.x += (v0.x + v1.x) + (v2.x + v3.x);
                acc.y += (v0.y + v1.y) + (v2.y + v3.y);
            }
        }
        for (; t < m; t++) {
            int s0 = __shfl_sync(0xFFFFFFFFu, idx, t);
            if (act) {
                float2 v = __half22float2(y[s0 * 24 + lc]);
                acc.x += v.x; acc.y += v.y;
            }
        }
    }

    float di = g_dinv[w];
    float vx = -3.0e38f, vy = -3.0e38f;
    if (act) {
        vx = fmaf(di, acc.x, b2[2 * l]);
        if (2 * l + 1 < F_OUT) vy = fmaf(di, acc.y, b2[2 * l + 1]);
    }
    float m = fmaxf(vx, vy);
    #pragma unroll
    for (int o = 16; o > 0; o >>= 1)
        m = fmaxf(m, __shfl_xor_sync(0xFFFFFFFFu, m, o));
    float s = 0.f;
    if (act) {
        s = expf(vx - m);
        if (2 * l + 1 < F_OUT) s += expf(vy - m);
    }
    #pragma unroll
    for (int o = 16; o > 0; o >>= 1)
        s += __shfl_xor_sync(0xFFFFFFFFu, s, o);
    float lse = m + logf(s);

    if (act) {
        out[w * F_OUT + 2 * l] = vx - lse;
        if (2 * l + 1 < F_OUT) out[w * F_OUT + 2 * l + 1] = vy - lse;
    }
}

// ---------------------------------------------------------------------------
// Launch (gemm1 forked to side stream; fused agg1+gemm2 on the tail)
// ---------------------------------------------------------------------------
extern "C" void kernel_launch(void* const* d_in, const int* in_sizes, int n_in,
                              void* d_out, int out_size) {
    const float* x  = (const float*)d_in[0];
    const int*   ei = (const int*)  d_in[1];
    const float* W1 = (const float*)d_in[2];
    const float* b1 = (const float*)d_in[3];
    const float* W2 = (const float*)d_in[4];
    const float* b2 = (const float*)d_in[5];
    float* out = (float*)d_out;

    int n = in_sizes[0] / F_IN;       // 100000
    int e = in_sizes[1] / 2;          // 1600000
    const int* src = ei;
    const int* dst = ei + e;

    static cudaStream_t s2 = nullptr;
    static cudaEvent_t ev_fork = nullptr, ev_join = nullptr;
    static void* degi_ptr = nullptr;
    if (s2 == nullptr) {
        cudaStreamCreateWithFlags(&s2, cudaStreamNonBlocking);
        cudaEventCreateWithFlags(&ev_fork, cudaEventDisableTiming);
        cudaEventCreateWithFlags(&ev_join, cudaEventDisableTiming);
        cudaGetSymbolAddress(&degi_ptr, g_degi);
    }

    const int B = 256;
    int nb = (n + SCAN_TPB - 1) / SCAN_TPB;   // 196 <= SCAN_TPB
    int e4 = e / 4;

    // Fork: GEMM1 (independent of CSR build) on side stream
    cudaEventRecord(ev_fork, 0);
    cudaStreamWaitEvent(s2, ev_fork, 0);
    gemm1_kernel<<<(n + 31) / 32, 256, 0, s2>>>(x, W1, n);
    cudaEventRecord(ev_join, s2);

    // Main stream: CSR build
    cudaMemsetAsync(degi_ptr, 0, (size_t)n * sizeof(int), 0);
    count4_kernel<<<(e4 + B - 1) / B, B>>>(dst, e4, e);
    scan_partial_kernel<<<nb, SCAN_TPB>>>(n);
    scan_write_kernel<<<nb, SCAN_TPB>>>(n, e);
    fill4_kernel<<<(e4 + B - 1) / B, B>>>(src, dst, e4, e);

    // Join: fused agg1+gemm2 needs CSR (main) and y1 (s2)
    cudaStreamWaitEvent(0, ev_join, 0);

    agg1g2_kernel<<<(n + 7) / 8, 256>>>(b1, W2, n);
    agg2_kernel<<<(n * 32 + B - 1) / B, B>>>(b2, out, n);
}

// round 12
// speedup vs baseline: 1.0474x; 1.0474x over previous
#include <cuda_runtime.h>
#include <cuda_bf16.h>
#include <cuda_fp16.h>
#include <math.h>

// Problem constants (fixed by the dataset)
#define NODES_MAX 100000
#define EDGES_MAX 1600000
#define F_IN   128
#define F_HID  64     // 32 half2 / 16 uint2
#define F_OUT  47
#define F_OUTP 48     // 24 half2 / 12 uint2

#define SCAN_TPB 512          // chunk size; 196 blocks for n=100000
#define SCAN_NB  256          // max scan blocks

typedef unsigned long long ull;

// ---------------------------------------------------------------------------
// f32x2 packed helpers (sm_100+ FFMA2 path — PTX only, per SASS_QUICKREF)
// ---------------------------------------------------------------------------
__device__ __forceinline__ ull pack2(float lo, float hi) {
    ull r; asm("mov.b64 %0, {%1, %2};" : "=l"(r) : "f"(lo), "f"(hi)); return r;
}
__device__ __forceinline__ void fma2(ull& acc, ull a, ull b) {
    asm("fma.rn.f32x2 %0, %1, %2, %0;" : "+l"(acc) : "l"(a), "l"(b));
}
__device__ __forceinline__ float2 unpack2(ull v) {
    float2 f; asm("mov.b64 {%0, %1}, %2;" : "=f"(f.x), "=f"(f.y) : "l"(v)); return f;
}

// ---------------------------------------------------------------------------
// Device scratch (no cudaMalloc allowed)
// ---------------------------------------------------------------------------
__device__ __half g_y1h[NODES_MAX * F_HID];   // x @ W1 (raw, fp16)
__device__ float  g_h  [NODES_MAX * F_HID];   // hidden after layer 1 (fp32)
__device__ __half g_y2h[NODES_MAX * F_OUTP];  // (h @ W2) * dinv[row] (fp16), col 47 = 0
__device__ float  g_dinv[NODES_MAX];
__device__ int    g_degi[NODES_MAX];
__device__ int    g_off [NODES_MAX + 1];
__device__ int    g_cursor[NODES_MAX];
__device__ int    g_csrc[EDGES_MAX];          // CSR by dst: source node ids
__device__ int    g_scanpub[SCAN_NB];         // per-block total+1 (0 = not ready)

// ---------------------------------------------------------------------------
// CSR build
// ---------------------------------------------------------------------------
__global__ void count4_kernel(const int* __restrict__ dst, int e4, int e) {
    int i = blockIdx.x * blockDim.x + threadIdx.x;
    if (i < e4) {
        int4 d = reinterpret_cast<const int4*>(dst)[i];
        atomicAdd(&g_degi[d.x], 1);
        atomicAdd(&g_degi[d.y], 1);
        atomicAdd(&g_degi[d.z], 1);
        atomicAdd(&g_degi[d.w], 1);
    }
    if (i == 0) {
        for (int k = e4 * 4; k < e; k++) atomicAdd(&g_degi[dst[k]], 1);
    }
}

// Single-kernel scan: per-block Hillis scan + publish(total) + all-to-all
// lookback (every predecessor total spin-read, tree-reduced to the base).
// All blocks co-resident (196 blocks, 512 thr, 4KB smem -> >=2 blocks/SM),
// so spinning on predecessors cannot deadlock.
__global__ __launch_bounds__(SCAN_TPB) void scan_fused_kernel(int n, int e) {
    __shared__ int s[SCAN_TPB];
    __shared__ int r[SCAN_TPB];
    int t = threadIdx.x, bid = blockIdx.x;
    int i = bid * SCAN_TPB + t;
    int d = (i < n) ? g_degi[i] : 0;
    s[t] = d;
    __syncthreads();
    // Hillis-Steele inclusive scan of this chunk
    for (int o = 1; o < SCAN_TPB; o <<= 1) {
        int u = (t >= o) ? s[t - o] : 0;
        __syncthreads();
        s[t] += u;
        __syncthreads();
    }
    // publish this block's total (as total+1 so 0 means "not ready")
    if (t == 0) atomicExch(&g_scanpub[bid], s[SCAN_TPB - 1] + 1);
    // lookback: thread t (< bid) spin-reads predecessor t's total
    int v = 0;
    if (t < bid) {
        do { v = atomicAdd(&g_scanpub[t], 0); } while (v == 0);
        v -= 1;
    }
    r[t] = v;
    __syncthreads();
    for (int o = SCAN_TPB / 2; o > 0; o >>= 1) {
        if (t < o) r[t] += r[t + o];
        __syncthreads();
    }
    int base = r[0];     // sum of predecessor totals (valid after last sync)
    if (i < n) {
        int off = base + s[t] - d;   // exclusive prefix
        g_off[i] = off;
        g_cursor[i] = off;
        g_dinv[i] = rsqrtf((float)(d + 1));
    }
    if (bid == 0 && t == 0) g_off[n] = e;
}

__global__ void fill4_kernel(const int* __restrict__ src, const int* __restrict__ dst,
                             int e4, int e) {
    int i = blockIdx.x * blockDim.x + threadIdx.x;
    if (i < e4) {
        int4 d = reinterpret_cast<const int4*>(dst)[i];
        int4 sv = reinterpret_cast<const int4*>(src)[i];
        int p0 = atomicAdd(&g_cursor[d.x], 1);
        int p1 = atomicAdd(&g_cursor[d.y], 1);
        int p2 = atomicAdd(&g_cursor[d.z], 1);
        int p3 = atomicAdd(&g_cursor[d.w], 1);
        g_csrc[p0] = sv.x;
        g_csrc[p1] = sv.y;
        g_csrc[p2] = sv.z;
        g_csrc[p3] = sv.w;
    }
    if (i == 0) {
        for (int k = e4 * 4; k < e; k++) {
            int p = atomicAdd(&g_cursor[dst[k]], 1);
            g_csrc[p] = src[k];
        }
    }
}

// ---------------------------------------------------------------------------
// GEMM1: y1h[n,64] = fp16(x[n,128] @ W1[128,64])   (raw; dinv applied in agg1)
// ---------------------------------------------------------------------------
#define XS_LD 129
__global__ __launch_bounds__(256) void gemm1_kernel(const float* __restrict__ x,
                                                    const float* __restrict__ W1,
                                                    int n) {
    __shared__ float Ws[F_IN * F_HID];        // 32 KB, [k][c]
    __shared__ float Xs[32 * XS_LD];          // ~16.5 KB, [r][k] padded
    int tid = threadIdx.x;
    int row0 = blockIdx.x * 32;

    for (int i = tid; i < F_IN * F_HID; i += 256) Ws[i] = W1[i];
    for (int i = tid; i < 32 * F_IN; i += 256) {
        int r = i >> 7, k = i & 127;
        int gr = row0 + r;
        Xs[r * XS_LD + k] = (gr < n) ? x[gr * F_IN + k] : 0.f;
    }
    __syncthreads();

    int tx = tid & 15;        // cols tx*4 .. tx*4+3 (pairs 2tx, 2tx+1)
    int ty = tid >> 4;        // 0..15, rows ty*2, ty*2+1
    ull acc00 = 0, acc01 = 0, acc10 = 0, acc11 = 0;   // bits(0,0) = (0.f,0.f)
    const ull* Ws2 = reinterpret_cast<const ull*>(Ws);  // 32 pairs per k-row
    int r0 = ty * 2, r1 = ty * 2 + 1;
    #pragma unroll 4
    for (int k = 0; k < F_IN; k++) {
        ull w0 = Ws2[k * 32 + tx * 2];
        ull w1 = Ws2[k * 32 + tx * 2 + 1];
        float a0 = Xs[r0 * XS_LD + k];
        float a1 = Xs[r1 * XS_LD + k];
        ull a0p = pack2(a0, a0);
        ull a1p = pack2(a1, a1);
        fma2(acc00, a0p, w0); fma2(acc01, a0p, w1);
        fma2(acc10, a1p, w0); fma2(acc11, a1p, w1);
    }
    int gr0 = row0 + r0, gr1 = row0 + r1;
    uint2* yp = reinterpret_cast<uint2*>(g_y1h);   // 16 uint2 per row
    if (gr0 < n) {
        float2 c0 = unpack2(acc00), c1 = unpack2(acc01);
        __half2 p0 = __floats2half2_rn(c0.x, c0.y);
        __half2 p1 = __floats2half2_rn(c1.x, c1.y);
        uint2 u;
        u.x = *reinterpret_cast<unsigned int*>(&p0);
        u.y = *reinterpret_cast<unsigned int*>(&p1);
        yp[gr0 * 16 + tx] = u;
    }
    if (gr1 < n) {
        float2 c0 = unpack2(acc10), c1 = unpack2(acc11);
        __half2 p0 = __floats2half2_rn(c0.x, c0.y);
        __half2 p1 = __floats2half2_rn(c1.x, c1.y);
        uint2 u;
        u.x = *reinterpret_cast<unsigned int*>(&p0);
        u.y = *reinterpret_cast<unsigned int*>(&p1);
        yp[gr1 * 16 + tx] = u;
    }
}

// ---------------------------------------------------------------------------
// Aggregation layer 1 (warp per dst node, fp16 gathers, edge-paired halves):
//   acc = dinv_d*y1[d] + sum_s dinv_s*y1[s] ; h[d] = relu(dinv_d*acc + b1)
// ---------------------------------------------------------------------------
__device__ __forceinline__ void acc4_fp16(float& f0, float& f1, float& f2, float& f3,
                                          uint2 a, float w) {
    __half2 h0 = *reinterpret_cast<__half2*>(&a.x);
    __half2 h1 = *reinterpret_cast<__half2*>(&a.y);
    float2 p0 = __half22float2(h0);
    float2 p1 = __half22float2(h1);
    f0 = fmaf(p0.x, w, f0); f1 = fmaf(p0.y, w, f1);
    f2 = fmaf(p1.x, w, f2); f3 = fmaf(p1.y, w, f3);
}

__global__ __launch_bounds__(256) void agg1_kernel(const float* __restrict__ b1, int n) {
    int w = (blockIdx.x * blockDim.x + threadIdx.x) >> 5;
    int l = threadIdx.x & 31;
    if (w >= n) return;
    int lh = l & 15, hh = l >> 4;
    const uint2* y = reinterpret_cast<const uint2*>(g_y1h);   // 16 per row

    float f0 = 0.f, f1 = 0.f, f2 = 0.f, f3 = 0.f;
    int beg = g_off[w], end = g_off[w + 1];
    for (int j = beg; j < end; j += 32) {
        int m = min(32, end - j);
        int idx = 0; float dv = 0.f;
        if (l < m) { idx = g_csrc[j + l]; dv = g_dinv[idx]; }
        int t = 0;
        for (; t + 7 < m; t += 8) {
            int   eA = t + hh, eB = t + 2 + hh, eC = t + 4 + hh, eD = t + 6 + hh;
            int   sA = __shfl_sync(0xFFFFFFFFu, idx, eA);
            float wA = __shfl_sync(0xFFFFFFFFu, dv,  eA);
            int   sB = __shfl_sync(0xFFFFFFFFu, idx, eB);
            float wB = __shfl_sync(0xFFFFFFFFu, dv,  eB);
            int   sC = __shfl_sync(0xFFFFFFFFu, idx, eC);
            float wC = __shfl_sync(0xFFFFFFFFu, dv,  eC);
            int   sD = __shfl_sync(0xFFFFFFFFu, idx, eD);
            float wD = __shfl_sync(0xFFFFFFFFu, dv,  eD);
            uint2 a = y[sA * 16 + lh];
            uint2 b = y[sB * 16 + lh];
            uint2 c = y[sC * 16 + lh];
            uint2 d = y[sD * 16 + lh];
            acc4_fp16(f0, f1, f2, f3, a, wA);
            acc4_fp16(f0, f1, f2, f3, b, wB);
            acc4_fp16(f0, f1, f2, f3, c, wC);
            acc4_fp16(f0, f1, f2, f3, d, wD);
        }
        for (; t + 3 < m; t += 4) {
            int   eA = t + hh, eB = t + 2 + hh;
            int   sA = __shfl_sync(0xFFFFFFFFu, idx, eA);
            float wA = __shfl_sync(0xFFFFFFFFu, dv,  eA);
            int   sB = __shfl_sync(0xFFFFFFFFu, idx, eB);
            float wB = __shfl_sync(0xFFFFFFFFu, dv,  eB);
            uint2 a = y[sA * 16 + lh];
            uint2 b = y[sB * 16 + lh];
            acc4_fp16(f0, f1, f2, f3, a, wA);
            acc4_fp16(f0, f1, f2, f3, b, wB);
        }
        for (; t < m; t += 2) {
            int   e0 = t + hh;
            int   se = min(e0, m - 1);
            int   s0 = __shfl_sync(0xFFFFFFFFu, idx, se);
            float w0 = __shfl_sync(0xFFFFFFFFu, dv,  se);
            if (e0 >= m) w0 = 0.f;
            uint2 a = y[s0 * 16 + lh];
            acc4_fp16(f0, f1, f2, f3, a, w0);
        }
    }
    f0 += __shfl_xor_sync(0xFFFFFFFFu, f0, 16);
    f1 += __shfl_xor_sync(0xFFFFFFFFu, f1, 16);
    f2 += __shfl_xor_sync(0xFFFFFFFFu, f2, 16);
    f3 += __shfl_xor_sync(0xFFFFFFFFu, f3, 16);

    float diw = g_dinv[w];
    uint2 sv = y[w * 16 + lh];            // self-loop term
    acc4_fp16(f0, f1, f2, f3, sv, diw);

    if (l < 16) {
        float4 bb = reinterpret_cast<const float4*>(b1)[lh];
        float4 hv;
        hv.x = fmaxf(fmaf(diw, f0, bb.x), 0.f);
        hv.y = fmaxf(fmaf(diw, f1, bb.y), 0.f);
        hv.z = fmaxf(fmaf(diw, f2, bb.z), 0.f);
        hv.w = fmaxf(fmaf(diw, f3, bb.w), 0.f);
        reinterpret_cast<float4*>(g_h)[w * 16 + lh] = hv;
    }
}

// ---------------------------------------------------------------------------
// GEMM2: y2h[n,48] = fp16((h[n,64] @ W2pad[64,48]) * dinv[row]), col 47 = 0
// ---------------------------------------------------------------------------
#define HS_LD 65
__global__ __launch_bounds__(192) void gemm2_kernel(const float* __restrict__ W2, int n) {
    __shared__ float Ws[F_HID * F_OUTP];      // 12 KB, [k][c]
    __shared__ float Hs[64 * HS_LD];          // ~16.6 KB, [r][k] padded
    int tid = threadIdx.x;
    int row0 = blockIdx.x * 64;

    for (int i = tid; i < F_HID * F_OUTP; i += 192) {
        int k = i / F_OUTP, c = i - k * F_OUTP;
        Ws[i] = (c < F_OUT) ? W2[k * F_OUT + c] : 0.f;
    }
    for (int i = tid; i < 64 * F_HID; i += 192) {
        int r = i >> 6, k = i & 63;
        int gr = row0 + r;
        Hs[r * HS_LD + k] = (gr < n) ? g_h[gr * F_HID + k] : 0.f;
    }
    __syncthreads();

    int tx = tid % 12;        // cols tx*4..tx*4+3 (pairs 2tx, 2tx+1)
    int ty = tid / 12;        // 0..15, rows ty*4..ty*4+3
    ull acc[4][2];
    #pragma unroll
    for (int i = 0; i < 4; i++) { acc[i][0] = 0; acc[i][1] = 0; }
    const ull* Ws2 = reinterpret_cast<const ull*>(Ws);   // 24 pairs per k-row

    #pragma unroll 4
    for (int k = 0; k < F_HID; k++) {
        ull w0 = Ws2[k * 24 + tx * 2];
        ull w1 = Ws2[k * 24 + tx * 2 + 1];
        #pragma unroll
        for (int i = 0; i < 4; i++) {
            float a = Hs[(ty * 4 + i) * HS_LD + k];
            ull ap = pack2(a, a);
            fma2(acc[i][0], ap, w0);
            fma2(acc[i][1], ap, w1);
        }
    }
    uint2* yp = reinterpret_cast<uint2*>(g_y2h);   // 12 uint2 per row
    #pragma unroll
    for (int i = 0; i < 4; i++) {
        int r = row0 + ty * 4 + i;
        if (r < n) {
            float di = g_dinv[r];
            float2 c0 = unpack2(acc[i][0]), c1 = unpack2(acc[i][1]);
            __half2 p0 = __floats2half2_rn(c0.x * di, c0.y * di);
            __half2 p1 = __floats2half2_rn(c1.x * di, c1.y * di);
            uint2 u;
            u.x = *reinterpret_cast<unsigned int*>(&p0);
            u.y = *reinterpret_cast<unsigned int*>(&p1);
            yp[r * 12 + tx] = u;
        }
    }
}

// ---------------------------------------------------------------------------
// Aggregation layer 2 + bias + log_softmax (warp per node, fp16 gathers):
//   z[d] = dinv[d]*(sum y2[s] + y2[d]) + b2 ; out = z - logsumexp(z)
// ---------------------------------------------------------------------------
__global__ __launch_bounds__(256) void agg2_kernel(const float* __restrict__ b2,
                                                   float* __restrict__ out, int n) {
    int w = (blockIdx.x * blockDim.x + threadIdx.x) >> 5;
    int l = threadIdx.x & 31;
    if (w >= n) return;
    const __half2* y = reinterpret_cast<const __half2*>(g_y2h);   // 24 per row
    bool act = (l < 24);
    int lc = act ? l : 0;

    float2 acc = make_float2(0.f, 0.f);
    if (act) {
        float2 v = __half22float2(y[w * 24 + l]);
        acc = v;                                   // self term (y2 pre-scaled)
    }
    int beg = g_off[w], end = g_off[w + 1];
    for (int j = beg; j < end; j += 32) {
        int m = min(32, end - j);
        int idx = (l < m) ? g_csrc[j + l] : 0;
        int t = 0;
        for (; t + 3 < m; t += 4) {
            int s0 = __shfl_sync(0xFFFFFFFFu, idx, t    );
            int s1 = __shfl_sync(0xFFFFFFFFu, idx, t + 1);
            int s2 = __shfl_sync(0xFFFFFFFFu, idx, t + 2);
            int s3 = __shfl_sync(0xFFFFFFFFu, idx, t + 3);
            if (act) {
                float2 v0 = __half22float2(y[s0 * 24 + lc]);
                float2 v1 = __half22float2(y[s1 * 24 + lc]);
                float2 v2 = __half22float2(y[s2 * 24 + lc]);
                float2 v3 = __half22float2(y[s3 * 24 + lc]);
                acc.x += (v0.x + v1.x) + (v2.x + v3.x);
                acc.y += (v0.y + v1.y) + (v2.y + v3.y);
            }
        }
        for (; t < m; t++) {
            int s0 = __shfl_sync(0xFFFFFFFFu, idx, t);
            if (act) {
                float2 v = __half22float2(y[s0 * 24 + lc]);
                acc.x += v.x; acc.y += v.y;
            }
        }
    }

    float di = g_dinv[w];
    float vx = -3.0e38f, vy = -3.0e38f;
    if (act) {
        vx = fmaf(di, acc.x, b2[2 * l]);
        if (2 * l + 1 < F_OUT) vy = fmaf(di, acc.y, b2[2 * l + 1]);
    }
    float m = fmaxf(vx, vy);
    #pragma unroll
    for (int o = 16; o > 0; o >>= 1)
        m = fmaxf(m, __shfl_xor_sync(0xFFFFFFFFu, m, o));
    float s = 0.f;
    if (act) {
        s = expf(vx - m);
        if (2 * l + 1 < F_OUT) s += expf(vy - m);
    }
    #pragma unroll
    for (int o = 16; o > 0; o >>= 1)
        s += __shfl_xor_sync(0xFFFFFFFFu, s, o);
    float lse = m + logf(s);

    if (act) {
        out[w * F_OUT + 2 * l] = vx - lse;
        if (2 * l + 1 < F_OUT) out[w * F_OUT + 2 * l + 1] = vy - lse;
    }
}

// ---------------------------------------------------------------------------
// Launch (gemm1 forked to side stream; single-kernel scan on main)
// ---------------------------------------------------------------------------
extern "C" void kernel_launch(void* const* d_in, const int* in_sizes, int n_in,
                              void* d_out, int out_size) {
    const float* x  = (const float*)d_in[0];
    const int*   ei = (const int*)  d_in[1];
    const float* W1 = (const float*)d_in[2];
    const float* b1 = (const float*)d_in[3];
    const float* W2 = (const float*)d_in[4];
    const float* b2 = (const float*)d_in[5];
    float* out = (float*)d_out;

    int n = in_sizes[0] / F_IN;       // 100000
    int e = in_sizes[1] / 2;          // 1600000
    const int* src = ei;
    const int* dst = ei + e;

    static cudaStream_t s2 = nullptr;
    static cudaEvent_t ev_fork = nullptr, ev_join = nullptr;
    static void* degi_ptr = nullptr;
    static void* scanpub_ptr = nullptr;
    if (s2 == nullptr) {
        cudaStreamCreateWithFlags(&s2, cudaStreamNonBlocking);
        cudaEventCreateWithFlags(&ev_fork, cudaEventDisableTiming);
        cudaEventCreateWithFlags(&ev_join, cudaEventDisableTiming);
        cudaGetSymbolAddress(&degi_ptr, g_degi);
        cudaGetSymbolAddress(&scanpub_ptr, g_scanpub);
    }

    const int B = 256;
    int nb = (n + SCAN_TPB - 1) / SCAN_TPB;   // 196 <= SCAN_NB
    int e4 = e / 4;

    // Fork: GEMM1 (independent of CSR build) on side stream
    cudaEventRecord(ev_fork, 0);
    cudaStreamWaitEvent(s2, ev_fork, 0);
    gemm1_kernel<<<(n + 31) / 32, 256, 0, s2>>>(x, W1, n);
    cudaEventRecord(ev_join, s2);

    // Main stream: CSR build
    cudaMemsetAsync(degi_ptr, 0, (size_t)n * sizeof(int), 0);
    cudaMemsetAsync(scanpub_ptr, 0, (size_t)SCAN_NB * sizeof(int), 0);
    count4_kernel<<<(e4 + B - 1) / B, B>>>(dst, e4, e);
    scan_fused_kernel<<<nb, SCAN_TPB>>>(n, e);
    fill4_kernel<<<(e4 + B - 1) / B, B>>>(src, dst, e4, e);

    // Join: agg1 needs CSR (main) and y1 (s2)
    cudaStreamWaitEvent(0, ev_join, 0);

    agg1_kernel<<<(n * 32 + B - 1) / B, B>>>(b1, n);
    gemm2_kernel<<<(n + 63) / 64, 192>>>(W2, n);
    agg2_kernel<<<(n * 32 + B - 1) / B, B>>>(b2, out, n);
}

// round 15
// speedup vs baseline: 1.0868x; 1.0376x over previous
#include <cuda_runtime.h>
#include <cuda_bf16.h>
#include <cuda_fp16.h>
#include <math.h>

// Problem constants (fixed by the dataset)
#define NODES_MAX 100000
#define EDGES_MAX 1600000
#define F_IN   128
#define F_HID  64     // 32 half2 / 16 uint2
#define F_OUT  47
#define F_OUTP 48     // logical out cols (col 47 = 0 pad)
#define Y2_STR 64     // y2h row stride in halves: 128B, line-aligned

#define SCAN_TPB 512          // chunk size; 196 blocks for n=100000
#define SCAN_NB  256          // max scan blocks

typedef unsigned long long ull;

// ---------------------------------------------------------------------------
// f32x2 packed helpers (sm_100+ FFMA2 path — PTX only, per SASS_QUICKREF)
// ---------------------------------------------------------------------------
__device__ __forceinline__ ull pack2(float lo, float hi) {
    ull r; asm("mov.b64 %0, {%1, %2};" : "=l"(r) : "f"(lo), "f"(hi)); return r;
}
__device__ __forceinline__ void fma2(ull& acc, ull a, ull b) {
    asm("fma.rn.f32x2 %0, %1, %2, %0;" : "+l"(acc) : "l"(a), "l"(b));
}
__device__ __forceinline__ float2 unpack2(ull v) {
    float2 f; asm("mov.b64 {%0, %1}, %2;" : "=f"(f.x), "=f"(f.y) : "l"(v)); return f;
}

// ---------------------------------------------------------------------------
// Device scratch (no cudaMalloc allowed)
// ---------------------------------------------------------------------------
__device__ __half g_y1h[NODES_MAX * F_HID];    // x @ W1; scaled in place by dinv
__device__ float  g_h  [NODES_MAX * F_HID];    // hidden after layer 1 (fp32)
__device__ __half g_y2h[NODES_MAX * Y2_STR];   // (h@W2)*dinv, cols 47..63 pad
__device__ float  g_dinv[NODES_MAX];
__device__ int    g_degi[NODES_MAX];
__device__ int    g_off [NODES_MAX + 1];
__device__ int    g_cursor[NODES_MAX];
__device__ int    g_csrc[EDGES_MAX];           // CSR by dst: source node ids
__device__ int    g_scanpub[SCAN_NB];          // per-block total+1 (0 = not ready)

// ---------------------------------------------------------------------------
// CSR build
// ---------------------------------------------------------------------------
__global__ void count4_kernel(const int* __restrict__ dst, int e4, int e) {
    int i = blockIdx.x * blockDim.x + threadIdx.x;
    if (i < e4) {
        int4 d = reinterpret_cast<const int4*>(dst)[i];
        atomicAdd(&g_degi[d.x], 1);
        atomicAdd(&g_degi[d.y], 1);
        atomicAdd(&g_degi[d.z], 1);
        atomicAdd(&g_degi[d.w], 1);
    }
    if (i == 0) {
        for (int k = e4 * 4; k < e; k++) atomicAdd(&g_degi[dst[k]], 1);
    }
}

// Single-kernel scan: per-block Hillis scan + publish(total) + all-to-all
// lookback. All 196 blocks co-resident -> no deadlock.
__global__ __launch_bounds__(SCAN_TPB) void scan_fused_kernel(int n, int e) {
    __shared__ int s[SCAN_TPB];
    __shared__ int r[SCAN_TPB];
    int t = threadIdx.x, bid = blockIdx.x;
    int i = bid * SCAN_TPB + t;
    int d = (i < n) ? g_degi[i] : 0;
    s[t] = d;
    __syncthreads();
    for (int o = 1; o < SCAN_TPB; o <<= 1) {
        int u = (t >= o) ? s[t - o] : 0;
        __syncthreads();
        s[t] += u;
        __syncthreads();
    }
    if (t == 0) atomicExch(&g_scanpub[bid], s[SCAN_TPB - 1] + 1);
    int v = 0;
    if (t < bid) {
        do { v = atomicAdd(&g_scanpub[t], 0); } while (v == 0);
        v -= 1;
    }
    r[t] = v;
    __syncthreads();
    for (int o = SCAN_TPB / 2; o > 0; o >>= 1) {
        if (t < o) r[t] += r[t + o];
        __syncthreads();
    }
    int base = r[0];
    if (i < n) {
        int off = base + s[t] - d;
        g_off[i] = off;
        g_cursor[i] = off;
        g_dinv[i] = rsqrtf((float)(d + 1));
    }
    if (bid == 0 && t == 0) g_off[n] = e;
}

__global__ void fill4_kernel(const int* __restrict__ src, const int* __restrict__ dst,
                             int e4, int e) {
    int i = blockIdx.x * blockDim.x + threadIdx.x;
    if (i < e4) {
        int4 d = reinterpret_cast<const int4*>(dst)[i];
        int4 sv = reinterpret_cast<const int4*>(src)[i];
        int p0 = atomicAdd(&g_cursor[d.x], 1);
        int p1 = atomicAdd(&g_cursor[d.y], 1);
        int p2 = atomicAdd(&g_cursor[d.z], 1);
        int p3 = atomicAdd(&g_cursor[d.w], 1);
        g_csrc[p0] = sv.x;
        g_csrc[p1] = sv.y;
        g_csrc[p2] = sv.z;
        g_csrc[p3] = sv.w;
    }
    if (i == 0) {
        for (int k = e4 * 4; k < e; k++) {
            int p = atomicAdd(&g_cursor[dst[k]], 1);
            g_csrc[p] = src[k];
        }
    }
}

// ---------------------------------------------------------------------------
// GEMM1: y1h[n,64] = fp16(x[n,128] @ W1[128,64])   (raw; scaled by scale_y1)
// ---------------------------------------------------------------------------
#define XS_LD 129
__global__ __launch_bounds__(256) void gemm1_kernel(const float* __restrict__ x,
                                                    const float* __restrict__ W1,
                                                    int n) {
    __shared__ float Ws[F_IN * F_HID];        // 32 KB, [k][c]
    __shared__ float Xs[32 * XS_LD];          // ~16.5 KB, [r][k] padded
    int tid = threadIdx.x;
    int row0 = blockIdx.x * 32;

    for (int i = tid; i < F_IN * F_HID; i += 256) Ws[i] = W1[i];
    for (int i = tid; i < 32 * F_IN; i += 256) {
        int r = i >> 7, k = i & 127;
        int gr = row0 + r;
        Xs[r * XS_LD + k] = (gr < n) ? x[gr * F_IN + k] : 0.f;
    }
    __syncthreads();

    int tx = tid & 15;        // cols tx*4 .. tx*4+3 (pairs 2tx, 2tx+1)
    int ty = tid >> 4;        // 0..15, rows ty*2, ty*2+1
    ull acc00 = 0, acc01 = 0, acc10 = 0, acc11 = 0;
    const ull* Ws2 = reinterpret_cast<const ull*>(Ws);  // 32 pairs per k-row
    int r0 = ty * 2, r1 = ty * 2 + 1;
    #pragma unroll 4
    for (int k = 0; k < F_IN; k++) {
        ull w0 = Ws2[k * 32 + tx * 2];
        ull w1 = Ws2[k * 32 + tx * 2 + 1];
        float a0 = Xs[r0 * XS_LD + k];
        float a1 = Xs[r1 * XS_LD + k];
        ull a0p = pack2(a0, a0);
        ull a1p = pack2(a1, a1);
        fma2(acc00, a0p, w0); fma2(acc01, a0p, w1);
        fma2(acc10, a1p, w0); fma2(acc11, a1p, w1);
    }
    int gr0 = row0 + r0, gr1 = row0 + r1;
    uint2* yp = reinterpret_cast<uint2*>(g_y1h);   // 16 uint2 per row
    if (gr0 < n) {
        float2 c0 = unpack2(acc00), c1 = unpack2(acc01);
        __half2 p0 = __floats2half2_rn(c0.x, c0.y);
        __half2 p1 = __floats2half2_rn(c1.x, c1.y);
        uint2 u;
        u.x = *reinterpret_cast<unsigned int*>(&p0);
        u.y = *reinterpret_cast<unsigned int*>(&p1);
        yp[gr0 * 16 + tx] = u;
    }
    if (gr1 < n) {
        float2 c0 = unpack2(acc10), c1 = unpack2(acc11);
        __half2 p0 = __floats2half2_rn(c0.x, c0.y);
        __half2 p1 = __floats2half2_rn(c1.x, c1.y);
        uint2 u;
        u.x = *reinterpret_cast<unsigned int*>(&p0);
        u.y = *reinterpret_cast<unsigned int*>(&p1);
        yp[gr1 * 16 + tx] = u;
    }
}

// Scale y1h in place by dinv[row]: z = dinv*xW1 (fp16). Side stream, under fill.
__global__ __launch_bounds__(256) void scale_y1_kernel(int n) {
    int i = blockIdx.x * blockDim.x + threadIdx.x;
    if (i >= n * 16) return;
    int r = i >> 4;
    float di = g_dinv[r];
    uint2* yp = reinterpret_cast<uint2*>(g_y1h);
    uint2 u = yp[i];
    __half2 h0 = *reinterpret_cast<__half2*>(&u.x);
    __half2 h1 = *reinterpret_cast<__half2*>(&u.y);
    float2 p0 = __half22float2(h0);
    float2 p1 = __half22float2(h1);
    __half2 q0 = __floats2half2_rn(p0.x * di, p0.y * di);
    __half2 q1 = __floats2half2_rn(p1.x * di, p1.y * di);
    u.x = *reinterpret_cast<unsigned int*>(&q0);
    u.y = *reinterpret_cast<unsigned int*>(&q1);
    yp[i] = u;
}

// ---------------------------------------------------------------------------
// Aggregation layer 1 (warp per dst node; prescaled fp16 rows, NO dinv gather):
//   acc = z[d] + sum_s z[s]   (z = dinv*xW1)
//   h[d] = relu(dinv_d * acc + b1)
// Half-warp edge pairing; per edge 1 line-aligned 128B row = 1 wavefront.
// ---------------------------------------------------------------------------
__device__ __forceinline__ void add4_fp16(float& f0, float& f1, float& f2, float& f3,
                                          uint2 a) {
    __half2 h0 = *reinterpret_cast<__half2*>(&a.x);
    __half2 h1 = *reinterpret_cast<__half2*>(&a.y);
    float2 p0 = __half22float2(h0);
    float2 p1 = __half22float2(h1);
    f0 += p0.x; f1 += p0.y;
    f2 += p1.x; f3 += p1.y;
}

__global__ __launch_bounds__(256) void agg1_kernel(const float* __restrict__ b1, int n) {
    int w = (blockIdx.x * blockDim.x + threadIdx.x) >> 5;
    int l = threadIdx.x & 31;
    if (w >= n) return;
    int lh = l & 15, hh = l >> 4;
    const uint2* y = reinterpret_cast<const uint2*>(g_y1h);   // 16 per row

    float f0 = 0.f, f1 = 0.f, f2 = 0.f, f3 = 0.f;
    int beg = g_off[w], end = g_off[w + 1];
    for (int j = beg; j < end; j += 32) {
        int m = min(32, end - j);
        int idx = (l < m) ? g_csrc[j + l] : 0;
        int t = 0;
        for (; t + 7 < m; t += 8) {
            int eA = t + hh, eB = t + 2 + hh, eC = t + 4 + hh, eD = t + 6 + hh;
            int sA = __shfl_sync(0xFFFFFFFFu, idx, eA);
            int sB = __shfl_sync(0xFFFFFFFFu, idx, eB);
            int sC = __shfl_sync(0xFFFFFFFFu, idx, eC);
            int sD = __shfl_sync(0xFFFFFFFFu, idx, eD);
            uint2 a = y[sA * 16 + lh];
            uint2 b = y[sB * 16 + lh];
            uint2 c = y[sC * 16 + lh];
            uint2 d = y[sD * 16 + lh];
            add4_fp16(f0, f1, f2, f3, a);
            add4_fp16(f0, f1, f2, f3, b);
            add4_fp16(f0, f1, f2, f3, c);
            add4_fp16(f0, f1, f2, f3, d);
        }
        for (; t + 3 < m; t += 4) {
            int eA = t + hh, eB = t + 2 + hh;
            int sA = __shfl_sync(0xFFFFFFFFu, idx, eA);
            int sB = __shfl_sync(0xFFFFFFFFu, idx, eB);
            uint2 a = y[sA * 16 + lh];
            uint2 b = y[sB * 16 + lh];
            add4_fp16(f0, f1, f2, f3, a);
            add4_fp16(f0, f1, f2, f3, b);
        }
        for (; t < m; t += 2) {
            int e0 = t + hh;
            int se = min(e0, m - 1);
            int s0 = __shfl_sync(0xFFFFFFFFu, idx, se);
            if (e0 < m) {
                uint2 a = y[s0 * 16 + lh];
                add4_fp16(f0, f1, f2, f3, a);
            }
        }
    }
    // fold the two half-warps (disjoint edge subsets)
    f0 += __shfl_xor_sync(0xFFFFFFFFu, f0, 16);
    f1 += __shfl_xor_sync(0xFFFFFFFFu, f1, 16);
    f2 += __shfl_xor_sync(0xFFFFFFFFu, f2, 16);
    f3 += __shfl_xor_sync(0xFFFFFFFFu, f3, 16);

    // self-loop term z[w] (added once, post-fold)
    uint2 sv = y[w * 16 + lh];
    add4_fp16(f0, f1, f2, f3, sv);

    float diw = g_dinv[w];
    if (l < 16) {
        float4 bb = reinterpret_cast<const float4*>(b1)[lh];
        float4 hv;
        hv.x = fmaxf(fmaf(diw, f0, bb.x), 0.f);
        hv.y = fmaxf(fmaf(diw, f1, bb.y), 0.f);
        hv.z = fmaxf(fmaf(diw, f2, bb.z), 0.f);
        hv.w = fmaxf(fmaf(diw, f3, bb.w), 0.f);
        reinterpret_cast<float4*>(g_h)[w * 16 + lh] = hv;
    }
}

// ---------------------------------------------------------------------------
// GEMM2: y2h[n, stride 64] = fp16((h[n,64] @ W2pad[64,48]) * dinv[row])
// ---------------------------------------------------------------------------
#define HS_LD 65
__global__ __launch_bounds__(192) void gemm2_kernel(const float* __restrict__ W2, int n) {
    __shared__ float Ws[F_HID * F_OUTP];      // 12 KB, [k][c]
    __shared__ float Hs[64 * HS_LD];          // ~16.6 KB, [r][k] padded
    int tid = threadIdx.x;
    int row0 = blockIdx.x * 64;

    for (int i = tid; i < F_HID * F_OUTP; i += 192) {
        int k = i / F_OUTP, c = i - k * F_OUTP;
        Ws[i] = (c < F_OUT) ? W2[k * F_OUT + c] : 0.f;
    }
    for (int i = tid; i < 64 * F_HID; i += 192) {
        int r = i >> 6, k = i & 63;
        int gr = row0 + r;
        Hs[r * HS_LD + k] = (gr < n) ? g_h[gr * F_HID + k] : 0.f;
    }
    __syncthreads();

    int tx = tid % 12;        // cols tx*4..tx*4+3 (pairs 2tx, 2tx+1)
    int ty = tid / 12;        // 0..15, rows ty*4..ty*4+3
    ull acc[4][2];
    #pragma unroll
    for (int i = 0; i < 4; i++) { acc[i][0] = 0; acc[i][1] = 0; }
    const ull* Ws2 = reinterpret_cast<const ull*>(Ws);   // 24 pairs per k-row

    #pragma unroll 4
    for (int k = 0; k < F_HID; k++) {
        ull w0 = Ws2[k * 24 + tx * 2];
        ull w1 = Ws2[k * 24 + tx * 2 + 1];
        #pragma unroll
        for (int i = 0; i < 4; i++) {
            float a = Hs[(ty * 4 + i) * HS_LD + k];
            ull ap = pack2(a, a);
            fma2(acc[i][0], ap, w0);
            fma2(acc[i][1], ap, w1);
        }
    }
    uint2* yp = reinterpret_cast<uint2*>(g_y2h);   // row stride = 16 uint2
    #pragma unroll
    for (int i = 0; i < 4; i++) {
        int r = row0 + ty * 4 + i;
        if (r < n) {
            float di = g_dinv[r];
            float2 c0 = unpack2(acc[i][0]), c1 = unpack2(acc[i][1]);
            __half2 p0 = __floats2half2_rn(c0.x * di, c0.y * di);
            __half2 p1 = __floats2half2_rn(c1.x * di, c1.y * di);
            uint2 u;
            u.x = *reinterpret_cast<unsigned int*>(&p0);
            u.y = *reinterpret_cast<unsigned int*>(&p1);
            yp[r * 16 + tx] = u;
        }
    }
}

// ---------------------------------------------------------------------------
// Aggregation layer 2 + bias + log_softmax (warp per node, fp16 gathers,
// 128B line-aligned rows -> 1 wavefront per edge gather):
//   z[d] = dinv[d]*(sum y2[s] + y2[d]) + b2 ; out = z - logsumexp(z)
// ---------------------------------------------------------------------------
__global__ __launch_bounds__(256) void agg2_kernel(const float* __restrict__ b2,
                                                   float* __restrict__ out, int n) {
    int w = (blockIdx.x * blockDim.x + threadIdx.x) >> 5;
    int l = threadIdx.x & 31;
    if (w >= n) return;
    const __half2* y = reinterpret_cast<const __half2*>(g_y2h);   // 32 per row
    bool act = (l < 24);
    int lc = act ? l : 0;

    float2 acc = make_float2(0.f, 0.f);
    if (act) {
        float2 v = __half22float2(y[w * 32 + l]);
        acc = v;                                   // self term (y2 pre-scaled)
    }
    int beg = g_off[w], end = g_off[w + 1];
    for (int j = beg; j < end; j += 32) {
        int m = min(32, end - j);
        int idx = (l < m) ? g_csrc[j + l] : 0;
        int t = 0;
        for (; t + 3 < m; t += 4) {
            int s0 = __shfl_sync(0xFFFFFFFFu, idx, t    );
            int s1 = __shfl_sync(0xFFFFFFFFu, idx, t + 1);
            int s2 = __shfl_sync(0xFFFFFFFFu, idx, t + 2);
            int s3 = __shfl_sync(0xFFFFFFFFu, idx, t + 3);
            if (act) {
                float2 v0 = __half22float2(y[s0 * 32 + lc]);
                float2 v1 = __half22float2(y[s1 * 32 + lc]);
                float2 v2 = __half22float2(y[s2 * 32 + lc]);
                float2 v3 = __half22float2(y[s3 * 32 + lc]);
                acc.x += (v0.x + v1.x) + (v2.x + v3.x);
                acc.y += (v0.y + v1.y) + (v2.y + v3.y);
            }
        }
        for (; t < m; t++) {
            int s0 = __shfl_sync(0xFFFFFFFFu, idx, t);
            if (act) {
                float2 v = __half22float2(y[s0 * 32 + lc]);
                acc.x += v.x; acc.y += v.y;
            }
        }
    }

    float di = g_dinv[w];
    float vx = -3.0e38f, vy = -3.0e38f;
    if (act) {
        vx = fmaf(di, acc.x, b2[2 * l]);
        if (2 * l + 1 < F_OUT) vy = fmaf(di, acc.y, b2[2 * l + 1]);
    }
    float m = fmaxf(vx, vy);
    #pragma unroll
    for (int o = 16; o > 0; o >>= 1)
        m = fmaxf(m, __shfl_xor_sync(0xFFFFFFFFu, m, o));
    float s = 0.f;
    if (act) {
        s = expf(vx - m);
        if (2 * l + 1 < F_OUT) s += expf(vy - m);
    }
    #pragma unroll
    for (int o = 16; o > 0; o >>= 1)
        s += __shfl_xor_sync(0xFFFFFFFFu, s, o);
    float lse = m + logf(s);

    if (act) {
        out[w * F_OUT + 2 * l] = vx - lse;
        if (2 * l + 1 < F_OUT) out[w * F_OUT + 2 * l + 1] = vy - lse;
    }
}

// ---------------------------------------------------------------------------
// Launch: gemm1 + scale_y1 on side stream (scale hidden under fill4)
// ---------------------------------------------------------------------------
extern "C" void kernel_launch(void* const* d_in, const int* in_sizes, int n_in,
                              void* d_out, int out_size) {
    const float* x  = (const float*)d_in[0];
    const int*   ei = (const int*)  d_in[1];
    const float* W1 = (const float*)d_in[2];
    const float* b1 = (const float*)d_in[3];
    const float* W2 = (const float*)d_in[4];
    const float* b2 = (const float*)d_in[5];
    float* out = (float*)d_out;

    int n = in_sizes[0] / F_IN;       // 100000
    int e = in_sizes[1] / 2;          // 1600000
    const int* src = ei;
    const int* dst = ei + e;

    static cudaStream_t s2 = nullptr;
    static cudaEvent_t ev_fork = nullptr, ev_scan = nullptr, ev_join = nullptr;
    static void* degi_ptr = nullptr;
    static void* scanpub_ptr = nullptr;
    if (s2 == nullptr) {
        cudaStreamCreateWithFlags(&s2, cudaStreamNonBlocking);
        cudaEventCreateWithFlags(&ev_fork, cudaEventDisableTiming);
        cudaEventCreateWithFlags(&ev_scan, cudaEventDisableTiming);
        cudaEventCreateWithFlags(&ev_join, cudaEventDisableTiming);
        cudaGetSymbolAddress(&degi_ptr, g_degi);
        cudaGetSymbolAddress(&scanpub_ptr, g_scanpub);
    }

    const int B = 256;
    int nb = (n + SCAN_TPB - 1) / SCAN_TPB;   // 196 <= SCAN_NB
    int e4 = e / 4;

    // Fork: GEMM1 (independent of CSR build) on side stream
    cudaEventRecord(ev_fork, 0);
    cudaStreamWaitEvent(s2, ev_fork, 0);
    gemm1_kernel<<<(n + 31) / 32, 256, 0, s2>>>(x, W1, n);

    // Main stream: CSR build
    cudaMemsetAsync(degi_ptr, 0, (size_t)n * sizeof(int), 0);
    cudaMemsetAsync(scanpub_ptr, 0, (size_t)SCAN_NB * sizeof(int), 0);
    count4_kernel<<<(e4 + B - 1) / B, B>>>(dst, e4, e);
    scan_fused_kernel<<<nb, SCAN_TPB>>>(n, e);
    cudaEventRecord(ev_scan, 0);              // dinv/off/cursor ready
    fill4_kernel<<<(e4 + B - 1) / B, B>>>(src, dst, e4, e);

    // Side stream: scale y1h by dinv (needs gemm1 + scan); hidden under fill4
    cudaStreamWaitEvent(s2, ev_scan, 0);
    scale_y1_kernel<<<(n * 16 + B - 1) / B, B, 0, s2>>>(n);
    cudaEventRecord(ev_join, s2);

    // Join: agg1 needs CSR (main) and scaled y1 (s2)
    cudaStreamWaitEvent(0, ev_join, 0);

    agg1_kernel<<<(n * 32 + B - 1) / B, B>>>(b1, n);
    gemm2_kernel<<<(n + 63) / 64, 192>>>(W2, n);
    agg2_kernel<<<(n * 32 + B - 1) / B, B>>>(b2, out, n);
}